// round 1
// baseline (speedup 1.0000x reference)
#include <cuda_runtime.h>
#include <math.h>

// Problem constants (from reference)
#define B_   64
#define C_   8
#define H_   256
#define W_   256
#define N_   200
#define NT   (B_ * N_)          // 12800 targets
#define HW   (H_ * W_)          // 65536
#define NUM_CLASSES 3

// Persistent scratch: 3 double accumulators [bbox, obj, cls]
__device__ double g_acc[3];

__global__ void yolo_zero_kernel() {
    if (threadIdx.x < 3) g_acc[threadIdx.x] = 0.0;
}

__device__ __forceinline__ float softplus_f(float x) {
    // log(1+e^x), numerically stable
    return fmaxf(x, 0.0f) + log1pf(expf(-fabsf(x)));
}

__global__ void __launch_bounds__(256) yolo_loss_kernel(
    const float* __restrict__ pred,
    const float* __restrict__ targets)
{
    int i = blockIdx.x * blockDim.x + threadIdx.x;

    float bbox = 0.0f, obj = 0.0f, clsl = 0.0f;

    if (i < NT) {
        int b = i / N_;
        const float* t = targets + (size_t)i * 5;
        float cid = t[0];
        float c0 = t[1], c1 = t[2], c2 = t[3], c3 = t[4];

        // valid = (cls_id >= 0) & (coords.sum(-1) > 0)
        float csum = ((c0 + c1) + c2) + c3;
        // xpix/ypix via truncating int cast (values positive)
        int xp = (int)(c0 * (float)W_);
        int yp = (int)(c1 * (float)H_);
        bool valid = (cid >= 0.0f) && (csum > 0.0f);
        bool inb = (xp >= 0) && (xp < W_) && (yp >= 0) && (yp < H_);

        if (valid && inb) {
            int xs = min(max(xp, 0), W_ - 1);
            int ys = min(max(yp, 0), H_ - 1);
            const float* base = pred + ((size_t)b * C_) * HW + (size_t)ys * W_ + xs;

            float p[C_];
            #pragma unroll
            for (int c = 0; c < C_; c++)
                p[c] = __ldg(base + (size_t)c * HW);   // 8 independent loads, MLP=8

            // bbox: mean squared error over 4 coords
            float d0 = p[0] - c0, d1 = p[1] - c1, d2 = p[2] - c2, d3 = p[3] - c3;
            bbox = 0.25f * (d0 * d0 + d1 * d1 + d2 * d2 + d3 * d3);

            // obj: bce(p4, 1) = softplus(p4) - p4 = softplus(-p4)
            obj = softplus_f(-p[4]);

            // cls: mean over 3 classes of bce(logit, onehot)
            int k = (int)fmaxf(cid, 0.0f);
            float s = 0.0f;
            #pragma unroll
            for (int c = 0; c < NUM_CLASSES; c++) {
                float l = p[5 + c];
                float z = (c == k) ? 1.0f : 0.0f;
                s += softplus_f(l) - l * z;
            }
            clsl = s * (1.0f / 3.0f);
        }
    }

    // Block reduction of the three partial sums
    __shared__ float sb[256], so[256], sc[256];
    int tid = threadIdx.x;
    sb[tid] = bbox; so[tid] = obj; sc[tid] = clsl;
    __syncthreads();
    #pragma unroll
    for (int off = 128; off > 0; off >>= 1) {
        if (tid < off) {
            sb[tid] += sb[tid + off];
            so[tid] += so[tid + off];
            sc[tid] += sc[tid + off];
        }
        __syncthreads();
    }
    if (tid == 0) {
        atomicAdd(&g_acc[0], (double)sb[0]);
        atomicAdd(&g_acc[1], (double)so[0]);
        atomicAdd(&g_acc[2], (double)sc[0]);
    }
}

__global__ void yolo_finalize_kernel(float* __restrict__ out) {
    double bs = g_acc[0], os = g_acc[1], cs = g_acc[2];
    double total = 0.05 * bs + 1.0 * os + 0.5 * cs;
    out[0] = (float)total;
    out[1] = (float)bs;
    out[2] = (float)os;
    out[3] = (float)cs;
}

extern "C" void kernel_launch(void* const* d_in, const int* in_sizes, int n_in,
                              void* d_out, int out_size)
{
    const float* pred    = (const float*)d_in[0];
    const float* targets = (const float*)d_in[1];
    float* out = (float*)d_out;

    yolo_zero_kernel<<<1, 32>>>();
    yolo_loss_kernel<<<(NT + 255) / 256, 256>>>(pred, targets);
    yolo_finalize_kernel<<<1, 1>>>(out);
}